// round 16
// baseline (speedup 1.0000x reference)
#include <cuda_runtime.h>
#include <cuda_bf16.h>
#include <math.h>

#define TT 1024
#define HH 2048
#define EE 64
#define KTOP 8
#define GG 8
#define GSZ 8
#define TGK 4
#define II 1024
#define ISH 2048
#define NPAIR (TT*KTOP)
#define MT 128
#define KC 64
#define NB 128            // N per CTA: moe1/shared1
#define NB2 256           // N per CTA: moe2/shared2
#define MAXTILES 160
#define SCALEF 2.5f
#define NTHR 512

typedef unsigned long long u64;
typedef unsigned int u32;

#if defined(__CUDA_ARCH_FEAT_SM103_ALL) || defined(__CUDA_ARCH_SPECIFIC__)
#define HAS_TC 1
#else
#define HAS_TC 0
#endif

#define IDESC_N128 ((1u<<4)|(1u<<7)|(1u<<10)|(16u<<17)|(8u<<24))
#define IDESC_N256 ((1u<<4)|(1u<<7)|(1u<<10)|(32u<<17)|(8u<<24))

// ---------------- device scratch ----------------
__device__ float d_logits[TT*EE];
__device__ int   d_topk_idx[NPAIR];
__device__ float d_topk_w[NPAIR];
__device__ int   d_counts[EE];
__device__ int   d_fill[EE];
__device__ int   d_tile_e[MAXTILES];
__device__ int   d_tile_start[MAXTILES];
__device__ int   d_tile_rows[MAXTILES];
__device__ int   d_ntiles;
__device__ int   d_pair_token[NPAIR];
__device__ float d_pair_w[NPAIR];
__device__ __nv_bfloat16 d_act_hi[(size_t)(NPAIR+MT)*II];
__device__ __nv_bfloat16 d_act_lo[(size_t)(NPAIR+MT)*II];
__device__ __nv_bfloat16 d_shact_hi[(size_t)TT*ISH];
__device__ __nv_bfloat16 d_shact_lo[(size_t)TT*ISH];

// ---------------- helpers ----------------
__device__ __forceinline__ u32 smem_u32(const void* p) {
    u32 a; asm("{ .reg .u64 t; cvta.to.shared.u64 t, %1; cvt.u32.u64 %0, t; }" : "=r"(a) : "l"(p));
    return a;
}
__device__ __forceinline__ u32 sw128(u32 off) { return off ^ ((off >> 3) & 0x70); }
__device__ __forceinline__ float siluf(float v) { return v / (1.f + __expf(-v)); }

__device__ __forceinline__ void split2(float a, float b, u32 &hi, u32 &lo) {
    u32 h;
    asm("cvt.rn.bf16x2.f32 %0, %1, %2;" : "=r"(h) : "f"(b), "f"(a));
    float ra = a - __uint_as_float(h << 16);
    float rb = b - __uint_as_float(h & 0xFFFF0000u);
    u32 l;
    asm("cvt.rn.bf16x2.f32 %0, %1, %2;" : "=r"(l) : "f"(rb), "f"(ra));
    hi = h; lo = l;
}
__device__ __forceinline__ u64 pack2f(float x, float y) {
    u64 r; asm("mov.b64 %0, {%1, %2};" : "=l"(r) : "f"(x), "f"(y)); return r;
}
__device__ __forceinline__ void unpack2f(u64 v, float &x, float &y) {
    asm("mov.b64 {%0, %1}, %2;" : "=f"(x), "=f"(y) : "l"(v));
}
__device__ __forceinline__ void fma2(u64 &d, u64 a, u64 b) {
    asm("fma.rn.f32x2 %0, %1, %2, %0;" : "+l"(d) : "l"(a), "l"(b));
}
__device__ __forceinline__ u64 sdesc(u32 addr) {
    return ((u64)2<<61) | ((u64)1<<46) | ((u64)64<<32) | ((u64)1<<16) | (((u64)(addr>>4)) & 0x3FFF);
}

#if HAS_TC
__device__ __forceinline__ u32 elect_one() {
    u32 pred;
    asm volatile("{\n\t.reg .pred p;\n\telect.sync _|p, 0xFFFFFFFF;\n\tselp.b32 %0, 1, 0, p;\n\t}" : "=r"(pred));
    return pred;
}
__device__ __forceinline__ void tmem_alloc(u32 dst, int n) {
    asm volatile("tcgen05.alloc.cta_group::1.sync.aligned.shared::cta.b32 [%0], %1;" :: "r"(dst), "r"(n) : "memory");
}
__device__ __forceinline__ void tmem_dealloc(u32 tm, int n) {
    asm volatile("tcgen05.dealloc.cta_group::1.sync.aligned.b32 %0, %1;" :: "r"(tm), "r"(n));
}
__device__ __forceinline__ void tmem_relinquish() {
    asm volatile("tcgen05.relinquish_alloc_permit.cta_group::1.sync.aligned;");
}
__device__ __forceinline__ void mma_bf16(u32 d, u64 a, u64 b, u32 id, u32 en) {
    asm volatile("{\n\t.reg .pred p;\n\tsetp.ne.u32 p, %4, 0;\n\t"
        "tcgen05.mma.cta_group::1.kind::f16 [%0], %1, %2, %3, {%5,%5,%5,%5}, p;\n\t}"
        :: "r"(d), "l"(a), "l"(b), "r"(id), "r"(en), "r"(0u) : "memory");
}
__device__ __forceinline__ void mma_commit(u32 mbar) {
    asm volatile("tcgen05.commit.cta_group::1.mbarrier::arrive::one.shared::cluster.b64 [%0];" :: "r"(mbar) : "memory");
}
__device__ __forceinline__ void tc_fence_before() {
    asm volatile("tcgen05.fence::before_thread_sync;" ::: "memory");
}
__device__ __forceinline__ void tc_fence_after() {
    asm volatile("tcgen05.fence::after_thread_sync;" ::: "memory");
}
__device__ __forceinline__ void tc_wait_ld() {
    asm volatile("tcgen05.wait::ld.sync.aligned;" ::: "memory");
}
#define LDTM_X32(r, a) \
    asm volatile("tcgen05.ld.sync.aligned.32x32b.x32.b32 " \
        "{%0,%1,%2,%3,%4,%5,%6,%7,%8,%9,%10,%11,%12,%13,%14,%15," \
        "%16,%17,%18,%19,%20,%21,%22,%23,%24,%25,%26,%27,%28,%29,%30,%31}, [%32];" \
        : "=r"((r)[0]),"=r"((r)[1]),"=r"((r)[2]),"=r"((r)[3]),"=r"((r)[4]),"=r"((r)[5]),"=r"((r)[6]),"=r"((r)[7]), \
          "=r"((r)[8]),"=r"((r)[9]),"=r"((r)[10]),"=r"((r)[11]),"=r"((r)[12]),"=r"((r)[13]),"=r"((r)[14]),"=r"((r)[15]), \
          "=r"((r)[16]),"=r"((r)[17]),"=r"((r)[18]),"=r"((r)[19]),"=r"((r)[20]),"=r"((r)[21]),"=r"((r)[22]),"=r"((r)[23]), \
          "=r"((r)[24]),"=r"((r)[25]),"=r"((r)[26]),"=r"((r)[27]),"=r"((r)[28]),"=r"((r)[29]),"=r"((r)[30]),"=r"((r)[31]) \
        : "r"(a))

// B tile slice held in registers (4x4 block per thread over 64k x 128n)
struct B4 { float4 v0, v1, v2, v3; };
__device__ __forceinline__ B4 load_b4(const float* __restrict__ B, int ld,
                                      int k0, int n0g, int tid) {
    int k = (tid & 15) * 4, n = (tid >> 4) * 4;
    const float* src = B + (size_t)(k0 + k) * ld + n0g + n;
    B4 r;
    r.v0 = *(const float4*)(src);
    r.v1 = *(const float4*)(src + ld);
    r.v2 = *(const float4*)(src + 2*ld);
    r.v3 = *(const float4*)(src + 3*ld);
    return r;
}
__device__ __forceinline__ void store_b4(char* smem, int off_h, int off_l,
                                         const B4& v, int tid, int n_loc) {
    int k = (tid & 15) * 4, n = (tid >> 4) * 4 + n_loc;
    #pragma unroll
    for (int j = 0; j < 4; j++) {
        float a0 = (j==0)?v.v0.x:(j==1)?v.v0.y:(j==2)?v.v0.z:v.v0.w;
        float a1 = (j==0)?v.v1.x:(j==1)?v.v1.y:(j==2)?v.v1.z:v.v1.w;
        float a2 = (j==0)?v.v2.x:(j==1)?v.v2.y:(j==2)?v.v2.z:v.v2.w;
        float a3 = (j==0)?v.v3.x:(j==1)?v.v3.y:(j==2)?v.v3.z:v.v3.w;
        u32 h01, l01, h23, l23;
        split2(a0, a1, h01, l01);
        split2(a2, a3, h23, l23);
        u32 sw = sw128((u32)((n + j) * 128 + k * 2));
        *(uint2*)(smem + off_h + sw) = make_uint2(h01, h23);
        *(uint2*)(smem + off_l + sw) = make_uint2(l01, l23);
    }
}
// A tile slice (bf16 hi/lo source), 16 elems per thread
struct A2 { uint4 h0, h1, l0, l1; };
__device__ __forceinline__ A2 load_a2(const __nv_bfloat16* ah_p, const __nv_bfloat16* al_p, int koff) {
    A2 r;
    r.h0 = *(const uint4*)(ah_p + koff);
    r.h1 = *(const uint4*)(ah_p + koff + 8);
    r.l0 = *(const uint4*)(al_p + koff);
    r.l1 = *(const uint4*)(al_p + koff + 8);
    return r;
}
__device__ __forceinline__ void store_a2(char* smem, int off_h, int off_l,
                                         const A2& v, int am, int aks) {
    u32 sw0 = sw128((u32)(am*128 + aks*2));
    u32 sw1 = sw128((u32)(am*128 + (aks + 8)*2));
    *(uint4*)(smem + off_h + sw0) = v.h0;
    *(uint4*)(smem + off_h + sw1) = v.h1;
    *(uint4*)(smem + off_l + sw0) = v.l0;
    *(uint4*)(smem + off_l + sw1) = v.l1;
}
#endif

__device__ __forceinline__ void mbar_init(u32 mbar, u32 cnt) {
    asm volatile("mbarrier.init.shared.b64 [%0], %1;" :: "r"(mbar), "r"(cnt) : "memory");
}
__device__ __forceinline__ void mbar_wait(u32 mbar, u32 parity) {
    asm volatile("{\n\t.reg .pred P;\n\t"
        "W%=:\n\t"
        "mbarrier.try_wait.parity.acquire.cta.shared::cta.b64 P, [%0], %1, 0x989680;\n\t"
        "@P bra.uni D%=;\n\t"
        "bra.uni W%=;\n\t"
        "D%=:\n\t}"
        :: "r"(mbar), "r"(parity) : "memory");
}
__device__ __forceinline__ void fence_async() {
    asm volatile("fence.proxy.async.shared::cta;" ::: "memory");
}

// smem layouts
#define SM_TMEM 0
#define SM_MBAR 8
#define SM_TOK  16
#define SM_W    528
#define SM_BASE 2048
// moe1/shared1 stage: A 32K, B0 32K, B1 32K (hi+lo interleaved at +16K)
#define OF_AH   0
#define OF_AL   16384
#define OF_B0H  32768
#define OF_B0L  49152
#define OF_B1H  65536
#define OF_B1L  81920
#define STG1    98304
// moe2/shared2 stage: A 32K, B(256 rows) hi 32K + lo 32K
#define OF2_AH  0
#define OF2_AL  16384
#define OF2_BH  32768
#define OF2_BL  65536
#define STG2    98304
#define SMEM_SZ1 (SM_BASE + 2*STG1)   // 198656
#define SMEM_SZ2 (SM_BASE + 2*STG2)   // 198656

// ---------------- small kernels ----------------
__global__ __launch_bounds__(256) void k_gate(const float* __restrict__ x,
                                              const float* __restrict__ gw) {
    __shared__ __align__(16) float As[16][66];
    __shared__ __align__(16) float Bs[16][64];
    int tid = threadIdx.x;
    if (blockIdx.x == 0 && tid < EE) d_counts[tid] = 0;   // fused k_zero
    int m0 = blockIdx.x * 64;
    int tx = tid & 15, ty = tid >> 4;
    int la_m = tid >> 2, la_k = (tid & 3) << 2;
    int lb_k = tid >> 4, lb_n = (tid & 15) << 2;
    const float* arow = x + (size_t)(m0 + la_m) * HH + la_k;
    float acc[4][4];
    #pragma unroll
    for (int i = 0; i < 4; i++) for (int j = 0; j < 4; j++) acc[i][j] = 0.f;
    for (int k0 = 0; k0 < HH; k0 += 16) {
        float4 av = *(const float4*)(arow + k0);
        As[la_k+0][la_m] = av.x; As[la_k+1][la_m] = av.y;
        As[la_k+2][la_m] = av.z; As[la_k+3][la_m] = av.w;
        *(float4*)&Bs[lb_k][lb_n] = *(const float4*)(gw + (size_t)(k0 + lb_k) * EE + lb_n);
        __syncthreads();
        #pragma unroll
        for (int kk = 0; kk < 16; kk++) {
            float4 b = *(const float4*)&Bs[kk][tx*4];
            #pragma unroll
            for (int i = 0; i < 4; i++) {
                float a = As[kk][ty*4+i];
                acc[i][0] += a*b.x; acc[i][1] += a*b.y; acc[i][2] += a*b.z; acc[i][3] += a*b.w;
            }
        }
        __syncthreads();
    }
    #pragma unroll
    for (int i = 0; i < 4; i++)
        *(float4*)(d_logits + (size_t)(m0 + ty*4 + i) * EE + tx*4) =
            make_float4(acc[i][0], acc[i][1], acc[i][2], acc[i][3]);
}

__global__ void k_route(const float* __restrict__ bias) {
    int t = blockIdx.x * blockDim.x + threadIdx.x;
    if (t >= TT) return;
    float s[EE], sb[EE];
    for (int e = 0; e < EE; e++) {
        float l = d_logits[(size_t)t*EE + e];
        float sg = 1.f / (1.f + expf(-l));
        s[e] = sg; sb[e] = sg + bias[e];
    }
    float gsc[GG];
    for (int g = 0; g < GG; g++) {
        float m1 = -INFINITY, m2 = -INFINITY;
        for (int j = 0; j < GSZ; j++) {
            float v = sb[g*GSZ + j];
            if (v > m1) { m2 = m1; m1 = v; } else if (v > m2) m2 = v;
        }
        gsc[g] = m1 + m2;
    }
    bool keep[GG];
    for (int g = 0; g < GG; g++) keep[g] = false;
    for (int r = 0; r < TGK; r++) {
        float best = -INFINITY; int bi = 0;
        for (int g = 0; g < GG; g++)
            if (!keep[g] && gsc[g] > best) { best = gsc[g]; bi = g; }
        keep[bi] = true;
    }
    for (int e = 0; e < EE; e++)
        if (!keep[e >> 3]) sb[e] = -INFINITY;
    int iv[KTOP]; float wv[KTOP]; float wsum = 0.f;
    for (int r = 0; r < KTOP; r++) {
        float best = -INFINITY; int bi = 0;
        for (int e = 0; e < EE; e++)
            if (sb[e] > best) { best = sb[e]; bi = e; }
        sb[bi] = -INFINITY;
        iv[r] = bi; wv[r] = s[bi]; wsum += s[bi];
    }
    float inv = SCALEF / wsum;
    for (int r = 0; r < KTOP; r++) {
        d_topk_idx[(size_t)t*KTOP + r] = iv[r];
        d_topk_w[(size_t)t*KTOP + r] = wv[r] * inv;
        atomicAdd(&d_counts[iv[r]], 1);
    }
}

// parallel 64-thread scan (pair offsets + tile list)
__global__ void k_scan() {
    int e = threadIdx.x;   // 64 threads
    int c = d_counts[e];
    __shared__ int s[EE], t[EE];
    s[e] = c;
    t[e] = (c + MT - 1) / MT;
    __syncthreads();
    for (int ofs = 1; ofs < EE; ofs <<= 1) {
        int vs = (e >= ofs) ? s[e - ofs] : 0;
        int vt = (e >= ofs) ? t[e - ofs] : 0;
        __syncthreads();
        s[e] += vs; t[e] += vt;
        __syncthreads();
    }
    int off = s[e] - c;
    int ntile = (c + MT - 1) / MT;
    int tb = t[e] - ntile;
    d_fill[e] = off;
    for (int j = 0, k = 0; j < c; j += MT, k++) {
        d_tile_e[tb + k] = e;
        d_tile_start[tb + k] = off + j;
        d_tile_rows[tb + k] = (c - j < MT) ? (c - j) : MT;
    }
    if (e == EE - 1) d_ntiles = t[EE - 1];
}

__global__ void k_scatter() {
    int i = blockIdx.x * blockDim.x + threadIdx.x;
    if (i >= NPAIR) return;
    int e = d_topk_idx[i];
    int pos = atomicAdd(&d_fill[e], 1);
    d_pair_token[pos] = i >> 3;
    d_pair_w[pos] = d_topk_w[i];
}

// ---------------- tcgen05 GEMM kernels ----------------

__global__ __launch_bounds__(NTHR)
#if HAS_TC
__cluster_dims__(1, 1, 1)
#endif
void k_moe1(const float* __restrict__ x,
            const float* __restrict__ wg,
            const float* __restrict__ wu) {
    int tile = blockIdx.x;
    if (tile >= d_ntiles) return;
    extern __shared__ char smem[];
    int tid = threadIdx.x;
    int e = d_tile_e[tile], start = d_tile_start[tile], rows = d_tile_rows[tile];
    int n0 = blockIdx.y * NB;
    const float* Bg = wg + (size_t)e * HH * II;
    const float* Bu = wu + (size_t)e * HH * II;
    int* s_tok = (int*)(smem + SM_TOK);
    if (tid < MT) s_tok[tid] = (tid < rows) ? d_pair_token[start + tid] : 0;
#if HAS_TC
    u32 sb = smem_u32(smem);
    int wid = tid >> 5, lid = tid & 31;
    if (tid == 0) mbar_init(sb + SM_MBAR, 1);
    if (wid == 0) { tmem_alloc(sb + SM_TMEM, 256); tmem_relinquish(); }
    __syncthreads();
    u32 tm; asm("ld.shared.b32 %0,[%1];" : "=r"(tm) : "r"(sb + SM_TMEM));

    int am = tid >> 2, aks = (tid & 3) * 16;
    const float* arow = x + (size_t)s_tok[am] * HH + aks;

    B4 bg_r = load_b4(Bg, II, 0, n0, tid);
    B4 bu_r = load_b4(Bu, II, 0, n0, tid);

    for (int c = 0; c < HH/KC; c++) {
        int st = SM_BASE + (c & 1) * STG1;
        #pragma unroll
        for (int r = 0; r < 4; r++) {
            float4 v = *(const float4*)(arow + c*KC + r*4);
            u32 h01, l01, h23, l23;
            split2(v.x, v.y, h01, l01); split2(v.z, v.w, h23, l23);
            u32 sw = sw128((u32)(am*128 + (aks + r*4)*2));
            *(uint2*)(smem + st + OF_AH + sw) = make_uint2(h01, h23);
            *(uint2*)(smem + st + OF_AL + sw) = make_uint2(l01, l23);
        }
        store_b4(smem, st + OF_B0H, st + OF_B0L, bg_r, tid, 0);
        store_b4(smem, st + OF_B1H, st + OF_B1L, bu_r, tid, 0);
        if (c + 1 < HH/KC) {
            bg_r = load_b4(Bg, II, (c+1)*KC, n0, tid);
            bu_r = load_b4(Bu, II, (c+1)*KC, n0, tid);
        }
        fence_async();
        tc_fence_before();
        if (c > 0) mbar_wait(sb + SM_MBAR, (c - 1) & 1);
        __syncthreads();
        if (wid == 0) {
            tc_fence_after();
            u64 ah = sdesc(sb + st + OF_AH), al = sdesc(sb + st + OF_AL);
            u64 gh = sdesc(sb + st + OF_B0H), gl = sdesc(sb + st + OF_B0L);
            u64 uh = sdesc(sb + st + OF_B1H), ul = sdesc(sb + st + OF_B1L);
            if (elect_one()) {
                #pragma unroll
                for (int s = 0; s < 4; s++) {
                    u32 en = (c == 0 && s == 0) ? 0u : 1u;
                    mma_bf16(tm +   0, ah + s*2, gh + s*2, IDESC_N128, en);
                    mma_bf16(tm +   0, ah + s*2, gl + s*2, IDESC_N128, 1u);
                    mma_bf16(tm +   0, al + s*2, gh + s*2, IDESC_N128, 1u);
                    mma_bf16(tm + 128, ah + s*2, uh + s*2, IDESC_N128, en);
                    mma_bf16(tm + 128, ah + s*2, ul + s*2, IDESC_N128, 1u);
                    mma_bf16(tm + 128, al + s*2, uh + s*2, IDESC_N128, 1u);
                }
                mma_commit(sb + SM_MBAR);
            }
        }
    }
    mbar_wait(sb + SM_MBAR, (HH/KC - 1) & 1);
    tc_fence_after();
    if (wid < 4) {
        int m = wid*32 + lid;
        #pragma unroll
        for (int pass = 0; pass < 4; pass++) {
            u32 rg[32], ru[32];
            LDTM_X32(rg, tm + pass*32);
            LDTM_X32(ru, tm + 128 + pass*32);
            tc_wait_ld();
            if (m < rows) {
                size_t base = (size_t)(start + m) * II + n0 + pass*32;
                #pragma unroll
                for (int j = 0; j < 32; j += 2) {
                    float g0 = __uint_as_float(rg[j]),   u0 = __uint_as_float(ru[j]);
                    float g1 = __uint_as_float(rg[j+1]), u1 = __uint_as_float(ru[j+1]);
                    float a0 = siluf(g0)*u0, a1 = siluf(g1)*u1;
                    u32 hi, lo; split2(a0, a1, hi, lo);
                    *(u32*)(d_act_hi + base + j) = hi;
                    *(u32*)(d_act_lo + base + j) = lo;
                }
            }
        }
    }
    __syncthreads();
    if (wid == 0) tmem_dealloc(tm, 256);
#else
    __syncthreads();
    int t2 = tid & 255;
    int tx = t2 & 15, ty = t2 >> 4;
    int la_m = t2 >> 2, la_k = (t2 & 3) << 2;
    int lb_k = t2 >> 4, lb_n = (t2 & 15) << 2;
    float (*As)[66]  = (float(*)[66])(smem + 2048);
    float (*Bs0)[64] = (float(*)[64])(smem + 2048 + 16*66*4);
    float (*Bs1)[64] = (float(*)[64])(smem + 2048 + 16*66*4 + 16*64*4);
    for (int ns = 0; ns < NB/64; ns++) {
        int n0s = n0 + ns*64;
        for (int sub = 0; sub < 2; sub++) {
            int mb = sub * 64;
            const float* arow = x + (size_t)s_tok[mb + la_m] * HH + la_k;
            u64 accg[4][2], accu[4][2];
            #pragma unroll
            for (int i = 0; i < 4; i++) { accg[i][0]=0ull; accg[i][1]=0ull; accu[i][0]=0ull; accu[i][1]=0ull; }
            for (int k0 = 0; k0 < HH; k0 += 16) {
                float4 av = *(const float4*)(arow + k0);
                As[la_k+0][la_m] = av.x; As[la_k+1][la_m] = av.y;
                As[la_k+2][la_m] = av.z; As[la_k+3][la_m] = av.w;
                *(float4*)&Bs0[lb_k][lb_n] = *(const float4*)(Bg + (size_t)(k0 + lb_k) * II + n0s + lb_n);
                *(float4*)&Bs1[lb_k][lb_n] = *(const float4*)(Bu + (size_t)(k0 + lb_k) * II + n0s + lb_n);
                __syncthreads();
                #pragma unroll
                for (int kk = 0; kk < 16; kk++) {
                    u64 a2[4];
                    #pragma unroll
                    for (int i = 0; i < 4; i++) { float a = As[kk][ty*4+i]; a2[i] = pack2f(a, a); }
                    ulonglong2 bg = *(const ulonglong2*)&Bs0[kk][tx*4];
                    ulonglong2 bu = *(const ulonglong2*)&Bs1[kk][tx*4];
                    #pragma unroll
                    for (int i = 0; i < 4; i++) {
                        fma2(accg[i][0], a2[i], bg.x); fma2(accg[i][1], a2[i], bg.y);
                        fma2(accu[i][0], a2[i], bu.x); fma2(accu[i][1], a2[i], bu.y);
                    }
                }
                __syncthreads();
            }
            #pragma unroll
            for (int i = 0; i < 4; i++) {
                int m = mb + ty*4 + i;
                if (m < rows) {
                    float g0,g1,g2,g3,u0,u1,u2,u3;
                    unpack2f(accg[i][0], g0, g1); unpack2f(accg[i][1], g2, g3);
                    unpack2f(accu[i][0], u0, u1); unpack2f(accu[i][1], u2, u3);
                    size_t base = (size_t)(start + m) * II + n0s + tx*4;
                    float a0 = siluf(g0)*u0, a1 = siluf(g1)*u1, a2v = siluf(g2)*u2, a3 = siluf(g3)*u3;
                    u32 hi, lo;
                    split2(a0, a1, hi, lo);
                    *(u32*)(d_act_hi + base) = hi; *(u32*)(d_act_lo + base) = lo;
                    split2(a2v, a3, hi, lo);
                    *(u32*)(d_act_hi + base + 2) = hi; *(u32*)(d_act_lo + base + 2) = lo;
                }
            }
            __syncthreads();
        }
    }
#endif
}

__global__ __launch_bounds__(NTHR)
#if HAS_TC
__cluster_dims__(1, 1, 1)
#endif
void k_moe2(const float* __restrict__ wd, float* __restrict__ out) {
    int tile = blockIdx.x;
    if (tile >= d_ntiles) return;
    extern __shared__ char smem[];
    int tid = threadIdx.x;
    int e = d_tile_e[tile], start = d_tile_start[tile], rows = d_tile_rows[tile];
    int n0 = blockIdx.y * NB2;
    const float* B = wd + (size_t)e * II * HH;
    int* s_tok = (int*)(smem + SM_TOK);
    float* s_w = (float*)(smem + SM_W);
    if (tid < MT) {
        s_tok[tid] = (tid < rows) ? d_pair_token[start + tid] : 0;
        s_w[tid]   = (tid < rows) ? d_pair_w[start + tid] : 0.f;
    }
#if HAS_TC
    u32 sb = smem_u32(smem);
    int wid = tid >> 5, lid = tid & 31;
    if (tid == 0) mbar_init(sb + SM_MBAR, 1);
    if (wid == 0) { tmem_alloc(sb + SM_TMEM, 256); tmem_relinquish(); }
    __syncthreads();
    u32 tm; asm("ld.shared.b32 %0,[%1];" : "=r"(tm) : "r"(sb + SM_TMEM));

    int am = tid >> 2, aks = (tid & 3) * 16;
    const __nv_bfloat16* ah_p = d_act_hi + (size_t)(start + am) * II + aks;
    const __nv_bfloat16* al_p = d_act_lo + (size_t)(start + am) * II + aks;

    A2 a_r = load_a2(ah_p, al_p, 0);
    B4 b0_r = load_b4(B, HH, 0, n0, tid);
    B4 b1_r = load_b4(B, HH, 0, n0 + 128, tid);

    for (int c = 0; c < II/KC; c++) {
        int st = SM_BASE + (c & 1) * STG2;
        store_a2(smem, st + OF2_AH, st + OF2_AL, a_r, am, aks);
        store_b4(smem, st + OF2_BH, st + OF2_BL, b0_r, tid, 0);
        store_b4(smem, st + OF2_BH, st + OF2_BL, b1_r, tid, 128);
        if (c + 1 < II/KC) {
            a_r = load_a2(ah_p, al_p, (c+1)*KC);
            b0_r = load_b4(B, HH, (c+1)*KC, n0, tid);
            b1_r = load_b4(B, HH, (c+1)*KC, n0 + 128, tid);
        }
        fence_async();
        tc_fence_before();
        if (c > 0) mbar_wait(sb + SM_MBAR, (c - 1) & 1);
        __syncthreads();
        if (wid == 0) {
            tc_fence_after();
            u64 ah = sdesc(sb + st + OF2_AH), al = sdesc(sb + st + OF2_AL);
            u64 bh = sdesc(sb + st + OF2_BH), bl = sdesc(sb + st + OF2_BL);
            if (elect_one()) {
                #pragma unroll
                for (int s = 0; s < 4; s++) {
                    u32 en = (c == 0 && s == 0) ? 0u : 1u;
                    mma_bf16(tm, ah + s*2, bh + s*2, IDESC_N256, en);
                    mma_bf16(tm, ah + s*2, bl + s*2, IDESC_N256, 1u);
                    mma_bf16(tm, al + s*2, bh + s*2, IDESC_N256, 1u);
                }
                mma_commit(sb + SM_MBAR);
            }
        }
    }
    mbar_wait(sb + SM_MBAR, (II/KC - 1) & 1);
    tc_fence_after();
    if (wid < 4) {
        int m = wid*32 + lid;
        #pragma unroll
        for (int pass = 0; pass < 8; pass++) {
            u32 r[32];
            LDTM_X32(r, tm + pass*32);
            tc_wait_ld();
            if (m < rows) {
                float w = s_w[m];
                float* o = out + (size_t)s_tok[m] * HH + n0 + pass*32;
                #pragma unroll
                for (int j = 0; j < 32; j++)
                    atomicAdd(o + j, w * __uint_as_float(r[j]));
            }
        }
    }
    __syncthreads();
    if (wid == 0) tmem_dealloc(tm, 256);
#else
    __syncthreads();
    int t2 = tid & 255;
    int tx = t2 & 15, ty = t2 >> 4;
    int la_m = t2 >> 2, la_k = (t2 & 3) << 2;
    int lb_k = t2 >> 4, lb_n = (t2 & 15) << 2;
    float (*As)[66]  = (float(*)[66])(smem + 2048);
    float (*Bs0)[64] = (float(*)[64])(smem + 2048 + 16*66*4);
    for (int ns = 0; ns < NB2/64; ns++) {
        int n0s = n0 + ns*64;
        for (int sub = 0; sub < 2; sub++) {
            int mb = sub * 64;
            const __nv_bfloat16* ahp = d_act_hi + (size_t)(start + mb + la_m) * II + la_k;
            const __nv_bfloat16* alp = d_act_lo + (size_t)(start + mb + la_m) * II + la_k;
            u64 acc[4][2];
            #pragma unroll
            for (int i = 0; i < 4; i++) { acc[i][0] = 0ull; acc[i][1] = 0ull; }
            for (int k0 = 0; k0 < II; k0 += 16) {
                #pragma unroll
                for (int j = 0; j < 4; j++)
                    As[la_k+j][la_m] = __bfloat162float(ahp[k0+j]) + __bfloat162float(alp[k0+j]);
                *(float4*)&Bs0[lb_k][lb_n] = *(const float4*)(B + (size_t)(k0 + lb_k) * HH + n0s + lb_n);
                __syncthreads();
                #pragma unroll
                for (int kk = 0; kk < 16; kk++) {
                    u64 a2[4];
                    #pragma unroll
                    for (int i = 0; i < 4; i++) { float a = As[kk][ty*4+i]; a2[i] = pack2f(a, a); }
                    ulonglong2 b = *(const ulonglong2*)&Bs0[kk][tx*4];
                    #pragma unroll
                    for (int i = 0; i < 4; i++) { fma2(acc[i][0], a2[i], b.x); fma2(acc[i][1], a2[i], b.y); }
                }
                __syncthreads();
            }
            if (tid < 256) {
                #pragma unroll
                for (int i = 0; i < 4; i++) {
                    int m = mb + ty*4 + i;
                    if (m < rows) {
                        float w = s_w[m];
                        float* o = out + (size_t)s_tok[m] * HH + n0s + tx*4;
                        float v0,v1,v2,v3;
                        unpack2f(acc[i][0], v0, v1); unpack2f(acc[i][1], v2, v3);
                        atomicAdd(o+0, w*v0); atomicAdd(o+1, w*v1);
                        atomicAdd(o+2, w*v2); atomicAdd(o+3, w*v3);
                    }
                }
            }
            __syncthreads();
        }
    }
#endif
}

__global__ __launch_bounds__(NTHR)
#if HAS_TC
__cluster_dims__(1, 1, 1)
#endif
void k_shared1(const float* __restrict__ x,
               const float* __restrict__ wg,
               const float* __restrict__ wu) {
    extern __shared__ char smem[];
    int tid = threadIdx.x;
    int m0 = blockIdx.x * MT, n0 = blockIdx.y * NB;
#if HAS_TC
    u32 sb = smem_u32(smem);
    int wid = tid >> 5, lid = tid & 31;
    if (tid == 0) mbar_init(sb + SM_MBAR, 1);
    if (wid == 0) { tmem_alloc(sb + SM_TMEM, 256); tmem_relinquish(); }
    __syncthreads();
    u32 tm; asm("ld.shared.b32 %0,[%1];" : "=r"(tm) : "r"(sb + SM_TMEM));

    int am = tid >> 2, aks = (tid & 3) * 16;
    const float* arow = x + (size_t)(m0 + am) * HH + aks;

    B4 bg_r = load_b4(wg, ISH, 0, n0, tid);
    B4 bu_r = load_b4(wu, ISH, 0, n0, tid);

    for (int c = 0; c < HH/KC; c++) {
        int st = SM_BASE + (c & 1) * STG1;
        #pragma unroll
        for (int r = 0; r < 4; r++) {
            float4 v = *(const float4*)(arow + c*KC + r*4);
            u32 h01, l01, h23, l23;
            split2(v.x, v.y, h01, l01); split2(v.z, v.w, h23, l23);
            u32 sw = sw128((u32)(am*128 + (aks + r*4)*2));
            *(uint2*)(smem + st + OF_AH + sw) = make_uint2(h01, h23);
            *(uint2*)(smem + st + OF_AL + sw) = make_uint2(l01, l23);
        }
        store_b4(smem, st + OF_B0H, st + OF_B0L, bg_r, tid, 0);
        store_b4(smem, st + OF_B1H, st + OF_B1L, bu_r, tid, 0);
        if (c + 1 < HH/KC) {
            bg_r = load_b4(wg, ISH, (c+1)*KC, n0, tid);
            bu_r = load_b4(wu, ISH, (c+1)*KC, n0, tid);
        }
        fence_async();
        tc_fence_before();
        if (c > 0) mbar_wait(sb + SM_MBAR, (c - 1) & 1);
        __syncthreads();
        if (wid == 0) {
            tc_fence_after();
            u64 ah = sdesc(sb + st + OF_AH), al = sdesc(sb + st + OF_AL);
            u64 gh = sdesc(sb + st + OF_B0H), gl = sdesc(sb + st + OF_B0L);
            u64 uh = sdesc(sb + st + OF_B1H), ul = sdesc(sb + st + OF_B1L);
            if (elect_one()) {
                #pragma unroll
                for (int s = 0; s < 4; s++) {
                    u32 en = (c == 0 && s == 0) ? 0u : 1u;
                    mma_bf16(tm +   0, ah + s*2, gh + s*2, IDESC_N128, en);
                    mma_bf16(tm +   0, ah + s*2, gl + s*2, IDESC_N128, 1u);
                    mma_bf16(tm +   0, al + s*2, gh + s*2, IDESC_N128, 1u);
                    mma_bf16(tm + 128, ah + s*2, uh + s*2, IDESC_N128, en);
                    mma_bf16(tm + 128, ah + s*2, ul + s*2, IDESC_N128, 1u);
                    mma_bf16(tm + 128, al + s*2, uh + s*2, IDESC_N128, 1u);
                }
                mma_commit(sb + SM_MBAR);
            }
        }
    }
    mbar_wait(sb + SM_MBAR, (HH/KC - 1) & 1);
    tc_fence_after();
    if (wid < 4) {
        int m = wid*32 + lid;
        #pragma unroll
        for (int pass = 0; pass < 4; pass++) {
            u32 rg[32], ru[32];
            LDTM_X32(rg, tm + pass*32);
            LDTM_X32(ru, tm + 128 + pass*32);
            tc_wait_ld();
            size_t base = (size_t)(m0 + m) * ISH + n0 + pass*32;
            #pragma unroll
            for (int j = 0; j < 32; j += 2) {
                float g0 = __uint_as_float(rg[j]),   u0 = __uint_as_float(ru[j]);
                float g1 = __uint_as_float(rg[j+1]), u1 = __uint_as_float(ru[j+1]);
                float a0 = siluf(g0)*u0, a1 = siluf(g1)*u1;
                u32 hi, lo; split2(a0, a1, hi, lo);
                *(u32*)(d_shact_hi + base + j) = hi;
                *(u32*)(d_shact_lo + base + j) = lo;
            }
        }
    }
    __syncthreads();
    if (wid == 0) tmem_dealloc(tm, 256);
#else
    int t2 = tid & 255;
    int tx = t2 & 15, ty = t2 >> 4;
    int la_m = t2 >> 2, la_k = (t2 & 3) << 2;
    int lb_k = t2 >> 4, lb_n = (t2 & 15) << 2;
    float (*As)[66]  = (float(*)[66])(smem + 2048);
    float (*Bs0)[64] = (float(*)[64])(smem + 2048 + 16*66*4);
    float (*Bs1)[64] = (float(*)[64])(smem + 2048 + 16*66*4 + 16*64*4);
    for (int ns = 0; ns < NB/64; ns++) {
        int n0s = n0 + ns*64;
        for (int sub = 0; sub < 2; sub++) {
            int mb = sub * 64;
            const float* arow = x + (size_t)(m0 + mb + la_m) * HH + la_k;
            u64 accg[4][2], accu[4][2];
            #pragma unroll
            for (int i = 0; i < 4; i++) { accg[i][0]=0ull; accg[i][1]=0ull; accu[i][0]=0ull; accu[i][1]=0ull; }
            for (int k0 = 0; k0 < HH; k0 += 16) {
                float4 av = *(const float4*)(arow + k0);
                As[la_k+0][la_m] = av.x; As[la_k+1][la_m] = av.y;
                As[la_k+2][la_m] = av.z; As[la_k+3][la_m] = av.w;
                *(float4*)&Bs0[lb_k][lb_n] = *(const float4*)(wg + (size_t)(k0 + lb_k) * ISH + n0s + lb_n);
                *(float4*)&Bs1[lb_k][lb_n] = *(const float4*)(wu + (size_t)(k0 + lb_k) * ISH + n0s + lb_n);
                __syncthreads();
                #pragma unroll
                for (int kk = 0; kk < 16; kk++) {
                    u64 a2[4];
                    #pragma unroll
                    for (int i = 0; i < 4; i++) { float a = As[kk][ty*4+i]; a2[i] = pack2f(a, a); }
                    ulonglong2 bg = *(const ulonglong2*)&Bs0[kk][tx*4];
                    ulonglong2 bu = *(const ulonglong2*)&Bs1[kk][tx*4];
                    #pragma unroll
                    for (int i = 0; i < 4; i++) {
                        fma2(accg[i][0], a2[i], bg.x); fma2(accg[i][1], a2[i], bg.y);
                        fma2(accu[i][0], a2[i], bu.x); fma2(accu[i][1], a2[i], bu.y);
                    }
                }
                __syncthreads();
            }
            #pragma unroll
            for (int i = 0; i < 4; i++) {
                float g0,g1,g2,g3,u0,u1,u2,u3;
                unpack2f(accg[i][0], g0, g1); unpack2f(accg[i][1], g2, g3);
                unpack2f(accu[i][0], u0, u1); unpack2f(accu[i][1], u2, u3);
                float a0 = siluf(g0)*u0, a1 = siluf(g1)*u1, a2v = siluf(g2)*u2, a3 = siluf(g3)*u3;
                size_t base = (size_t)(m0 + mb + ty*4 + i) * ISH + n0s + tx*4;
                u32 hi, lo;
                split2(a0, a1, hi, lo);
                *(u32*)(d_shact_hi + base) = hi; *(u32*)(d_shact_lo + base) = lo;
                split2(a2v, a3, hi, lo);
                *(u32*)(d_shact_hi + base + 2) = hi; *(u32*)(d_shact_lo + base + 2) = lo;
            }
            __syncthreads();
        }
    }
#endif
}

__global__ __launch_bounds__(NTHR)
#if HAS_TC
__cluster_dims__(1, 1, 1)
#endif
void k_shared2(const float* __restrict__ wd, float* __restrict__ out) {
    extern __shared__ char smem[];
    int tid = threadIdx.x;
    int m0 = blockIdx.x * MT, n0 = blockIdx.y * NB2;
#if HAS_TC
    u32 sb = smem_u32(smem);
    int wid = tid >> 5, lid = tid & 31;
    if (tid == 0) mbar_init(sb + SM_MBAR, 1);
    if (wid == 0) { tmem_alloc(sb + SM_TMEM, 256); tmem_relinquish(); }
    __syncthreads();
    u32 tm; asm("ld.shared.b32 %0,[%1];" : "=r"(tm) : "r"(sb + SM_TMEM));

    int am = tid >> 2, aks = (tid & 3) * 16;
    const __nv_bfloat16* ah_p = d_shact_hi + (size_t)(m0 + am) * ISH + aks;
    const __nv_bfloat16* al_p = d_shact_lo + (size_t)(m0 + am) * ISH + aks;

    A2 a_r = load_a2(ah_p, al_p, 0);
    B4 b0_r = load_b4(wd, HH, 0, n0, tid);
    B4 b1_r = load_b4(wd, HH, 0, n0 + 128, tid);

    for (int c = 0; c < ISH/KC; c++) {
        int st = SM_BASE + (c & 1) * STG2;
        store_a2(smem, st + OF2_AH, st + OF2_AL, a_r, am, aks);
        store_b4(smem, st + OF2_BH, st + OF2_BL, b0_r, tid, 0);
        store_b4(smem, st + OF2_BH, st + OF2_BL, b1_r, tid, 128);
        if (c + 1 < ISH/KC) {
            a_r = load_a2(ah_p, al_p, (c+1)*KC);
            b0_r = load_b4(wd, HH, (c+1)*KC, n0, tid);
            b1_r = load_b4(wd, HH, (c+1)*KC, n0 + 128, tid);
        }
        fence_async();
        tc_fence_before();
        if (c > 0) mbar_wait(sb + SM_MBAR, (c - 1) & 1);
        __syncthreads();
        if (wid == 0) {
            tc_fence_after();
            u64 ah = sdesc(sb + st + OF2_AH), al = sdesc(sb + st + OF2_AL);
            u64 bh = sdesc(sb + st + OF2_BH), bl = sdesc(sb + st + OF2_BL);
            if (elect_one()) {
                #pragma unroll
                for (int s = 0; s < 4; s++) {
                    u32 en = (c == 0 && s == 0) ? 0u : 1u;
                    mma_bf16(tm, ah + s*2, bh + s*2, IDESC_N256, en);
                    mma_bf16(tm, ah + s*2, bl + s*2, IDESC_N256, 1u);
                    mma_bf16(tm, al + s*2, bh + s*2, IDESC_N256, 1u);
                }
                mma_commit(sb + SM_MBAR);
            }
        }
    }
    mbar_wait(sb + SM_MBAR, (ISH/KC - 1) & 1);
    tc_fence_after();
    if (wid < 4) {
        int m = wid*32 + lid;
        #pragma unroll
        for (int pass = 0; pass < 8; pass++) {
            u32 r[32];
            LDTM_X32(r, tm + pass*32);
            tc_wait_ld();
            float* o = out + (size_t)(m0 + m) * HH + n0 + pass*32;
            #pragma unroll
            for (int j = 0; j < 32; j += 4)
                *(float4*)(o + j) = make_float4(
                    __uint_as_float(r[j]),   __uint_as_float(r[j+1]),
                    __uint_as_float(r[j+2]), __uint_as_float(r[j+3]));
        }
    }
    __syncthreads();
    if (wid == 0) tmem_dealloc(tm, 256);
#else
    int t2 = tid & 255;
    int tx = t2 & 15, ty = t2 >> 4;
    int la_m = t2 >> 2, la_k = (t2 & 3) << 2;
    int lb_k = t2 >> 4, lb_n = (t2 & 15) << 2;
    float (*As)[66]  = (float(*)[66])(smem + 2048);
    float (*Bs0)[64] = (float(*)[64])(smem + 2048 + 16*66*4);
    for (int ns = 0; ns < NB2/64; ns++) {
        int n0s = n0 + ns*64;
        for (int sub = 0; sub < 2; sub++) {
            int mb = sub * 64;
            const __nv_bfloat16* ahp = d_shact_hi + (size_t)(m0 + mb + la_m) * ISH + la_k;
            const __nv_bfloat16* alp = d_shact_lo + (size_t)(m0 + mb + la_m) * ISH + la_k;
            u64 acc[4][2];
            #pragma unroll
            for (int i = 0; i < 4; i++) { acc[i][0] = 0ull; acc[i][1] = 0ull; }
            for (int k0 = 0; k0 < ISH; k0 += 16) {
                #pragma unroll
                for (int j = 0; j < 4; j++)
                    As[la_k+j][la_m] = __bfloat162float(ahp[k0+j]) + __bfloat162float(alp[k0+j]);
                *(float4*)&Bs0[lb_k][lb_n] = *(const float4*)(wd + (size_t)(k0 + lb_k) * HH + n0s + lb_n);
                __syncthreads();
                #pragma unroll
                for (int kk = 0; kk < 16; kk++) {
                    u64 a2[4];
                    #pragma unroll
                    for (int i = 0; i < 4; i++) { float a = As[kk][ty*4+i]; a2[i] = pack2f(a, a); }
                    ulonglong2 b = *(const ulonglong2*)&Bs0[kk][tx*4];
                    #pragma unroll
                    for (int i = 0; i < 4; i++) { fma2(acc[i][0], a2[i], b.x); fma2(acc[i][1], a2[i], b.y); }
                }
                __syncthreads();
            }
            if (tid < 256) {
                #pragma unroll
                for (int i = 0; i < 4; i++) {
                    float v0,v1,v2,v3;
                    unpack2f(acc[i][0], v0, v1); unpack2f(acc[i][1], v2, v3);
                    float* o = out + (size_t)(m0 + mb + ty*4 + i) * HH + n0s + tx*4;
                    o[0] = v0; o[1] = v1; o[2] = v2; o[3] = v3;
                }
            }
            __syncthreads();
        }
    }
#endif
}

extern "C" void kernel_launch(void* const* d_in, const int* in_sizes, int n_in,
                              void* d_out, int out_size) {
    const float* x    = (const float*)d_in[0];
    const float* gw   = (const float*)d_in[1];
    const float* bias = (const float*)d_in[2];
    const float* wg   = (const float*)d_in[3];
    const float* wu   = (const float*)d_in[4];
    const float* wd   = (const float*)d_in[5];
    const float* wsg  = (const float*)d_in[6];
    const float* wsu  = (const float*)d_in[7];
    const float* wsd  = (const float*)d_in[8];
    float* out = (float*)d_out;

    cudaFuncSetAttribute(k_moe1,    cudaFuncAttributeMaxDynamicSharedMemorySize, SMEM_SZ1);
    cudaFuncSetAttribute(k_moe2,    cudaFuncAttributeMaxDynamicSharedMemorySize, SMEM_SZ2);
    cudaFuncSetAttribute(k_shared1, cudaFuncAttributeMaxDynamicSharedMemorySize, SMEM_SZ1);
    cudaFuncSetAttribute(k_shared2, cudaFuncAttributeMaxDynamicSharedMemorySize, SMEM_SZ2);

    k_gate<<<16, 256>>>(x, gw);
    k_route<<<4, 256>>>(bias);
    k_scan<<<1, 64>>>();
    k_scatter<<<NPAIR/256, 256>>>();
    k_moe1<<<dim3(MAXTILES, II/NB), NTHR, SMEM_SZ1>>>(x, wg, wu);
    k_shared1<<<dim3(TT/MT, ISH/NB), NTHR, SMEM_SZ1>>>(x, wsg, wsu);
    k_shared2<<<dim3(TT/MT, HH/NB2), NTHR, SMEM_SZ2>>>(wsd, out);
    k_moe2<<<dim3(MAXTILES, HH/NB2), NTHR, SMEM_SZ2>>>(wd, out);
}

// round 17
// speedup vs baseline: 1.0379x; 1.0379x over previous
#include <cuda_runtime.h>
#include <cuda_bf16.h>
#include <math.h>

#define TT 1024
#define HH 2048
#define EE 64
#define KTOP 8
#define GG 8
#define GSZ 8
#define TGK 4
#define II 1024
#define ISH 2048
#define NPAIR (TT*KTOP)
#define MT 128
#define KC 64
#define NB 128
#define MAXTILES 160
#define SCALEF 2.5f
#define NTHR 512

typedef unsigned long long u64;
typedef unsigned int u32;

#if defined(__CUDA_ARCH_FEAT_SM103_ALL) || defined(__CUDA_ARCH_SPECIFIC__)
#define HAS_TC 1
#else
#define HAS_TC 0
#endif

#define IDESC_N128 ((1u<<4)|(1u<<7)|(1u<<10)|(16u<<17)|(8u<<24))

// ---------------- device scratch ----------------
__device__ float d_logits[TT*EE];
__device__ int   d_topk_idx[NPAIR];
__device__ float d_topk_w[NPAIR];
__device__ int   d_counts[EE];
__device__ int   d_fill[EE];
__device__ int   d_tile_e[MAXTILES];
__device__ int   d_tile_start[MAXTILES];
__device__ int   d_tile_rows[MAXTILES];
__device__ int   d_ntiles;
__device__ int   d_pair_token[NPAIR];
__device__ float d_pair_w[NPAIR];
__device__ __nv_bfloat16 d_act_hi[(size_t)(NPAIR+MT)*II];
__device__ __nv_bfloat16 d_act_lo[(size_t)(NPAIR+MT)*II];
__device__ __nv_bfloat16 d_shact_hi[(size_t)TT*ISH];
__device__ __nv_bfloat16 d_shact_lo[(size_t)TT*ISH];

// ---------------- helpers ----------------
__device__ __forceinline__ u32 smem_u32(const void* p) {
    u32 a; asm("{ .reg .u64 t; cvta.to.shared.u64 t, %1; cvt.u32.u64 %0, t; }" : "=r"(a) : "l"(p));
    return a;
}
__device__ __forceinline__ u32 sw128(u32 off) { return off ^ ((off >> 3) & 0x70); }
__device__ __forceinline__ float siluf(float v) { return v / (1.f + __expf(-v)); }

__device__ __forceinline__ void split2(float a, float b, u32 &hi, u32 &lo) {
    u32 h;
    asm("cvt.rn.bf16x2.f32 %0, %1, %2;" : "=r"(h) : "f"(b), "f"(a));
    float ra = a - __uint_as_float(h << 16);
    float rb = b - __uint_as_float(h & 0xFFFF0000u);
    u32 l;
    asm("cvt.rn.bf16x2.f32 %0, %1, %2;" : "=r"(l) : "f"(rb), "f"(ra));
    hi = h; lo = l;
}
__device__ __forceinline__ u64 pack2f(float x, float y) {
    u64 r; asm("mov.b64 %0, {%1, %2};" : "=l"(r) : "f"(x), "f"(y)); return r;
}
__device__ __forceinline__ void unpack2f(u64 v, float &x, float &y) {
    asm("mov.b64 {%0, %1}, %2;" : "=f"(x), "=f"(y) : "l"(v));
}
__device__ __forceinline__ void fma2(u64 &d, u64 a, u64 b) {
    asm("fma.rn.f32x2 %0, %1, %2, %0;" : "+l"(d) : "l"(a), "l"(b));
}
__device__ __forceinline__ u64 sdesc(u32 addr) {
    return ((u64)2<<61) | ((u64)1<<46) | ((u64)64<<32) | ((u64)1<<16) | (((u64)(addr>>4)) & 0x3FFF);
}

#if HAS_TC
__device__ __forceinline__ u32 elect_one() {
    u32 pred;
    asm volatile("{\n\t.reg .pred p;\n\telect.sync _|p, 0xFFFFFFFF;\n\tselp.b32 %0, 1, 0, p;\n\t}" : "=r"(pred));
    return pred;
}
__device__ __forceinline__ void tmem_alloc(u32 dst, int n) {
    asm volatile("tcgen05.alloc.cta_group::1.sync.aligned.shared::cta.b32 [%0], %1;" :: "r"(dst), "r"(n) : "memory");
}
__device__ __forceinline__ void tmem_dealloc(u32 tm, int n) {
    asm volatile("tcgen05.dealloc.cta_group::1.sync.aligned.b32 %0, %1;" :: "r"(tm), "r"(n));
}
__device__ __forceinline__ void tmem_relinquish() {
    asm volatile("tcgen05.relinquish_alloc_permit.cta_group::1.sync.aligned;");
}
__device__ __forceinline__ void mma_bf16(u32 d, u64 a, u64 b, u32 id, u32 en) {
    asm volatile("{\n\t.reg .pred p;\n\tsetp.ne.u32 p, %4, 0;\n\t"
        "tcgen05.mma.cta_group::1.kind::f16 [%0], %1, %2, %3, {%5,%5,%5,%5}, p;\n\t}"
        :: "r"(d), "l"(a), "l"(b), "r"(id), "r"(en), "r"(0u) : "memory");
}
__device__ __forceinline__ void mma_commit(u32 mbar) {
    asm volatile("tcgen05.commit.cta_group::1.mbarrier::arrive::one.shared::cluster.b64 [%0];" :: "r"(mbar) : "memory");
}
__device__ __forceinline__ void tc_fence_before() {
    asm volatile("tcgen05.fence::before_thread_sync;" ::: "memory");
}
__device__ __forceinline__ void tc_fence_after() {
    asm volatile("tcgen05.fence::after_thread_sync;" ::: "memory");
}
__device__ __forceinline__ void tc_wait_ld() {
    asm volatile("tcgen05.wait::ld.sync.aligned;" ::: "memory");
}
#define LDTM_X32(r, a) \
    asm volatile("tcgen05.ld.sync.aligned.32x32b.x32.b32 " \
        "{%0,%1,%2,%3,%4,%5,%6,%7,%8,%9,%10,%11,%12,%13,%14,%15," \
        "%16,%17,%18,%19,%20,%21,%22,%23,%24,%25,%26,%27,%28,%29,%30,%31}, [%32];" \
        : "=r"((r)[0]),"=r"((r)[1]),"=r"((r)[2]),"=r"((r)[3]),"=r"((r)[4]),"=r"((r)[5]),"=r"((r)[6]),"=r"((r)[7]), \
          "=r"((r)[8]),"=r"((r)[9]),"=r"((r)[10]),"=r"((r)[11]),"=r"((r)[12]),"=r"((r)[13]),"=r"((r)[14]),"=r"((r)[15]), \
          "=r"((r)[16]),"=r"((r)[17]),"=r"((r)[18]),"=r"((r)[19]),"=r"((r)[20]),"=r"((r)[21]),"=r"((r)[22]),"=r"((r)[23]), \
          "=r"((r)[24]),"=r"((r)[25]),"=r"((r)[26]),"=r"((r)[27]),"=r"((r)[28]),"=r"((r)[29]),"=r"((r)[30]),"=r"((r)[31]) \
        : "r"(a))

// B tile slice held in registers (4x4 block per thread over 64k x 128n)
struct B4 { float4 v0, v1, v2, v3; };
__device__ __forceinline__ B4 load_b4(const float* __restrict__ B, int ld,
                                      int k0, int n0g, int tid) {
    int k = (tid & 15) * 4, n = (tid >> 4) * 4;
    const float* src = B + (size_t)(k0 + k) * ld + n0g + n;
    B4 r;
    r.v0 = *(const float4*)(src);
    r.v1 = *(const float4*)(src + ld);
    r.v2 = *(const float4*)(src + 2*ld);
    r.v3 = *(const float4*)(src + 3*ld);
    return r;
}
__device__ __forceinline__ void store_b4(char* smem, int off_h, int off_l,
                                         const B4& v, int tid) {
    int k = (tid & 15) * 4, n = (tid >> 4) * 4;
    #pragma unroll
    for (int j = 0; j < 4; j++) {
        float a0 = (j==0)?v.v0.x:(j==1)?v.v0.y:(j==2)?v.v0.z:v.v0.w;
        float a1 = (j==0)?v.v1.x:(j==1)?v.v1.y:(j==2)?v.v1.z:v.v1.w;
        float a2 = (j==0)?v.v2.x:(j==1)?v.v2.y:(j==2)?v.v2.z:v.v2.w;
        float a3 = (j==0)?v.v3.x:(j==1)?v.v3.y:(j==2)?v.v3.z:v.v3.w;
        u32 h01, l01, h23, l23;
        split2(a0, a1, h01, l01);
        split2(a2, a3, h23, l23);
        u32 sw = sw128((u32)((n + j) * 128 + k * 2));
        *(uint2*)(smem + off_h + sw) = make_uint2(h01, h23);
        *(uint2*)(smem + off_l + sw) = make_uint2(l01, l23);
    }
}
// A tile slice (bf16 hi/lo source), 16 elems per thread
struct A2 { uint4 h0, h1, l0, l1; };
__device__ __forceinline__ A2 load_a2(const __nv_bfloat16* ah_p, const __nv_bfloat16* al_p, int koff) {
    A2 r;
    r.h0 = *(const uint4*)(ah_p + koff);
    r.h1 = *(const uint4*)(ah_p + koff + 8);
    r.l0 = *(const uint4*)(al_p + koff);
    r.l1 = *(const uint4*)(al_p + koff + 8);
    return r;
}
__device__ __forceinline__ void store_a2(char* smem, int off_h, int off_l,
                                         const A2& v, int am, int aks) {
    u32 sw0 = sw128((u32)(am*128 + aks*2));
    u32 sw1 = sw128((u32)(am*128 + (aks + 8)*2));
    *(uint4*)(smem + off_h + sw0) = v.h0;
    *(uint4*)(smem + off_h + sw1) = v.h1;
    *(uint4*)(smem + off_l + sw0) = v.l0;
    *(uint4*)(smem + off_l + sw1) = v.l1;
}
#endif

__device__ __forceinline__ void mbar_init(u32 mbar, u32 cnt) {
    asm volatile("mbarrier.init.shared.b64 [%0], %1;" :: "r"(mbar), "r"(cnt) : "memory");
}
__device__ __forceinline__ void mbar_wait(u32 mbar, u32 parity) {
    asm volatile("{\n\t.reg .pred P;\n\t"
        "W%=:\n\t"
        "mbarrier.try_wait.parity.acquire.cta.shared::cta.b64 P, [%0], %1, 0x989680;\n\t"
        "@P bra.uni D%=;\n\t"
        "bra.uni W%=;\n\t"
        "D%=:\n\t}"
        :: "r"(mbar), "r"(parity) : "memory");
}
__device__ __forceinline__ void fence_async() {
    asm volatile("fence.proxy.async.shared::cta;" ::: "memory");
}

// smem layout: header + 2 stages.
#define SM_TMEM 0
#define SM_MBAR 8
#define SM_TOK  16
#define SM_W    528
#define SM_BASE 2048
#define OF_AH   0
#define OF_AL   16384
#define OF_B0H  32768
#define OF_B0L  49152
#define OF_B1H  65536
#define OF_B1L  81920
#define STG1    98304
#define STG2    65536
#define SMEM_SZ1 (SM_BASE + 2*STG1)
#define SMEM_SZ2 (SM_BASE + 2*STG2)

// ---------------- small kernels ----------------
__global__ __launch_bounds__(256) void k_gate(const float* __restrict__ x,
                                              const float* __restrict__ gw) {
    __shared__ __align__(16) float As[16][66];
    __shared__ __align__(16) float Bs[16][64];
    int tid = threadIdx.x;
    if (blockIdx.x == 0 && tid < EE) d_counts[tid] = 0;   // fused k_zero
    int m0 = blockIdx.x * 64;
    int tx = tid & 15, ty = tid >> 4;
    int la_m = tid >> 2, la_k = (tid & 3) << 2;
    int lb_k = tid >> 4, lb_n = (tid & 15) << 2;
    const float* arow = x + (size_t)(m0 + la_m) * HH + la_k;
    float acc[4][4];
    #pragma unroll
    for (int i = 0; i < 4; i++) for (int j = 0; j < 4; j++) acc[i][j] = 0.f;
    for (int k0 = 0; k0 < HH; k0 += 16) {
        float4 av = *(const float4*)(arow + k0);
        As[la_k+0][la_m] = av.x; As[la_k+1][la_m] = av.y;
        As[la_k+2][la_m] = av.z; As[la_k+3][la_m] = av.w;
        *(float4*)&Bs[lb_k][lb_n] = *(const float4*)(gw + (size_t)(k0 + lb_k) * EE + lb_n);
        __syncthreads();
        #pragma unroll
        for (int kk = 0; kk < 16; kk++) {
            float4 b = *(const float4*)&Bs[kk][tx*4];
            #pragma unroll
            for (int i = 0; i < 4; i++) {
                float a = As[kk][ty*4+i];
                acc[i][0] += a*b.x; acc[i][1] += a*b.y; acc[i][2] += a*b.z; acc[i][3] += a*b.w;
            }
        }
        __syncthreads();
    }
    #pragma unroll
    for (int i = 0; i < 4; i++)
        *(float4*)(d_logits + (size_t)(m0 + ty*4 + i) * EE + tx*4) =
            make_float4(acc[i][0], acc[i][1], acc[i][2], acc[i][3]);
}

__global__ void k_route(const float* __restrict__ bias) {
    int t = blockIdx.x * blockDim.x + threadIdx.x;
    if (t >= TT) return;
    float s[EE], sb[EE];
    for (int e = 0; e < EE; e++) {
        float l = d_logits[(size_t)t*EE + e];
        float sg = 1.f / (1.f + expf(-l));
        s[e] = sg; sb[e] = sg + bias[e];
    }
    float gsc[GG];
    for (int g = 0; g < GG; g++) {
        float m1 = -INFINITY, m2 = -INFINITY;
        for (int j = 0; j < GSZ; j++) {
            float v = sb[g*GSZ + j];
            if (v > m1) { m2 = m1; m1 = v; } else if (v > m2) m2 = v;
        }
        gsc[g] = m1 + m2;
    }
    bool keep[GG];
    for (int g = 0; g < GG; g++) keep[g] = false;
    for (int r = 0; r < TGK; r++) {
        float best = -INFINITY; int bi = 0;
        for (int g = 0; g < GG; g++)
            if (!keep[g] && gsc[g] > best) { best = gsc[g]; bi = g; }
        keep[bi] = true;
    }
    for (int e = 0; e < EE; e++)
        if (!keep[e >> 3]) sb[e] = -INFINITY;
    int iv[KTOP]; float wv[KTOP]; float wsum = 0.f;
    for (int r = 0; r < KTOP; r++) {
        float best = -INFINITY; int bi = 0;
        for (int e = 0; e < EE; e++)
            if (sb[e] > best) { best = sb[e]; bi = e; }
        sb[bi] = -INFINITY;
        iv[r] = bi; wv[r] = s[bi]; wsum += s[bi];
    }
    float inv = SCALEF / wsum;
    for (int r = 0; r < KTOP; r++) {
        d_topk_idx[(size_t)t*KTOP + r] = iv[r];
        d_topk_w[(size_t)t*KTOP + r] = wv[r] * inv;
        atomicAdd(&d_counts[iv[r]], 1);
    }
}

// parallel 64-thread scan (pair offsets + tile list)
__global__ void k_scan() {
    int e = threadIdx.x;   // 64 threads
    int c = d_counts[e];
    __shared__ int s[EE], t[EE];
    s[e] = c;
    t[e] = (c + MT - 1) / MT;
    __syncthreads();
    for (int ofs = 1; ofs < EE; ofs <<= 1) {
        int vs = (e >= ofs) ? s[e - ofs] : 0;
        int vt = (e >= ofs) ? t[e - ofs] : 0;
        __syncthreads();
        s[e] += vs; t[e] += vt;
        __syncthreads();
    }
    int off = s[e] - c;
    int ntile = (c + MT - 1) / MT;
    int tb = t[e] - ntile;
    d_fill[e] = off;
    for (int j = 0, k = 0; j < c; j += MT, k++) {
        d_tile_e[tb + k] = e;
        d_tile_start[tb + k] = off + j;
        d_tile_rows[tb + k] = (c - j < MT) ? (c - j) : MT;
    }
    if (e == EE - 1) d_ntiles = t[EE - 1];
}

__global__ void k_scatter() {
    int i = blockIdx.x * blockDim.x + threadIdx.x;
    if (i >= NPAIR) return;
    int e = d_topk_idx[i];
    int pos = atomicAdd(&d_fill[e], 1);
    d_pair_token[pos] = i >> 3;
    d_pair_w[pos] = d_topk_w[i];
}

// ---------------- tcgen05 GEMM kernels (double-buffered + reg-prefetch) ----------------

__global__ __launch_bounds__(NTHR)
#if HAS_TC
__cluster_dims__(1, 1, 1)
#endif
void k_moe1(const float* __restrict__ x,
            const float* __restrict__ wg,
            const float* __restrict__ wu) {
    int tile = blockIdx.x;
    if (tile >= d_ntiles) return;
    extern __shared__ char smem[];
    int tid = threadIdx.x;
    int e = d_tile_e[tile], start = d_tile_start[tile], rows = d_tile_rows[tile];
    int n0 = blockIdx.y * NB;
    const float* Bg = wg + (size_t)e * HH * II;
    const float* Bu = wu + (size_t)e * HH * II;
    int* s_tok = (int*)(smem + SM_TOK);
    if (tid < MT) s_tok[tid] = (tid < rows) ? d_pair_token[start + tid] : 0;
#if HAS_TC
    u32 sb = smem_u32(smem);
    int wid = tid >> 5, lid = tid & 31;
    if (tid == 0) mbar_init(sb + SM_MBAR, 1);
    if (wid == 0) { tmem_alloc(sb + SM_TMEM, 256); tmem_relinquish(); }
    __syncthreads();
    u32 tm; asm("ld.shared.b32 %0,[%1];" : "=r"(tm) : "r"(sb + SM_TMEM));

    int am = tid >> 2, aks = (tid & 3) * 16;
    const float* arow = x + (size_t)s_tok[am] * HH + aks;

    B4 bg_r = load_b4(Bg, II, 0, n0, tid);
    B4 bu_r = load_b4(Bu, II, 0, n0, tid);

    for (int c = 0; c < HH/KC; c++) {
        int st = SM_BASE + (c & 1) * STG1;
        #pragma unroll
        for (int r = 0; r < 4; r++) {
            float4 v = *(const float4*)(arow + c*KC + r*4);
            u32 h01, l01, h23, l23;
            split2(v.x, v.y, h01, l01); split2(v.z, v.w, h23, l23);
            u32 sw = sw128((u32)(am*128 + (aks + r*4)*2));
            *(uint2*)(smem + st + OF_AH + sw) = make_uint2(h01, h23);
            *(uint2*)(smem + st + OF_AL + sw) = make_uint2(l01, l23);
        }
        store_b4(smem, st + OF_B0H, st + OF_B0L, bg_r, tid);
        store_b4(smem, st + OF_B1H, st + OF_B1L, bu_r, tid);
        if (c + 1 < HH/KC) {
            bg_r = load_b4(Bg, II, (c+1)*KC, n0, tid);
            bu_r = load_b4(Bu, II, (c+1)*KC, n0, tid);
        }
        fence_async();
        tc_fence_before();
        if (c > 0) mbar_wait(sb + SM_MBAR, (c - 1) & 1);
        __syncthreads();
        if (wid == 0) {
            tc_fence_after();
            u64 ah = sdesc(sb + st + OF_AH), al = sdesc(sb + st + OF_AL);
            u64 gh = sdesc(sb + st + OF_B0H), gl = sdesc(sb + st + OF_B0L);
            u64 uh = sdesc(sb + st + OF_B1H), ul = sdesc(sb + st + OF_B1L);
            if (elect_one()) {
                #pragma unroll
                for (int s = 0; s < 4; s++) {
                    u32 en = (c == 0 && s == 0) ? 0u : 1u;
                    mma_bf16(tm +   0, ah + s*2, gh + s*2, IDESC_N128, en);
                    mma_bf16(tm +   0, ah + s*2, gl + s*2, IDESC_N128, 1u);
                    mma_bf16(tm +   0, al + s*2, gh + s*2, IDESC_N128, 1u);
                    mma_bf16(tm + 128, ah + s*2, uh + s*2, IDESC_N128, en);
                    mma_bf16(tm + 128, ah + s*2, ul + s*2, IDESC_N128, 1u);
                    mma_bf16(tm + 128, al + s*2, uh + s*2, IDESC_N128, 1u);
                }
                mma_commit(sb + SM_MBAR);
            }
        }
    }
    mbar_wait(sb + SM_MBAR, (HH/KC - 1) & 1);
    tc_fence_after();
    if (wid < 4) {
        int m = wid*32 + lid;
        #pragma unroll
        for (int pass = 0; pass < 4; pass++) {
            u32 rg[32], ru[32];
            LDTM_X32(rg, tm + pass*32);
            LDTM_X32(ru, tm + 128 + pass*32);
            tc_wait_ld();
            if (m < rows) {
                size_t base = (size_t)(start + m) * II + n0 + pass*32;
                #pragma unroll
                for (int j = 0; j < 32; j += 2) {
                    float g0 = __uint_as_float(rg[j]),   u0 = __uint_as_float(ru[j]);
                    float g1 = __uint_as_float(rg[j+1]), u1 = __uint_as_float(ru[j+1]);
                    float a0 = siluf(g0)*u0, a1 = siluf(g1)*u1;
                    u32 hi, lo; split2(a0, a1, hi, lo);
                    *(u32*)(d_act_hi + base + j) = hi;
                    *(u32*)(d_act_lo + base + j) = lo;
                }
            }
        }
    }
    __syncthreads();
    if (wid == 0) tmem_dealloc(tm, 256);
#else
    __syncthreads();
    int t2 = tid & 255;
    int tx = t2 & 15, ty = t2 >> 4;
    int la_m = t2 >> 2, la_k = (t2 & 3) << 2;
    int lb_k = t2 >> 4, lb_n = (t2 & 15) << 2;
    float (*As)[66]  = (float(*)[66])(smem + 2048);
    float (*Bs0)[64] = (float(*)[64])(smem + 2048 + 16*66*4);
    float (*Bs1)[64] = (float(*)[64])(smem + 2048 + 16*66*4 + 16*64*4);
    for (int ns = 0; ns < NB/64; ns++) {
        int n0s = n0 + ns*64;
        for (int sub = 0; sub < 2; sub++) {
            int mb = sub * 64;
            const float* arow = x + (size_t)s_tok[mb + la_m] * HH + la_k;
            u64 accg[4][2], accu[4][2];
            #pragma unroll
            for (int i = 0; i < 4; i++) { accg[i][0]=0ull; accg[i][1]=0ull; accu[i][0]=0ull; accu[i][1]=0ull; }
            for (int k0 = 0; k0 < HH; k0 += 16) {
                float4 av = *(const float4*)(arow + k0);
                As[la_k+0][la_m] = av.x; As[la_k+1][la_m] = av.y;
                As[la_k+2][la_m] = av.z; As[la_k+3][la_m] = av.w;
                *(float4*)&Bs0[lb_k][lb_n] = *(const float4*)(Bg + (size_t)(k0 + lb_k) * II + n0s + lb_n);
                *(float4*)&Bs1[lb_k][lb_n] = *(const float4*)(Bu + (size_t)(k0 + lb_k) * II + n0s + lb_n);
                __syncthreads();
                #pragma unroll
                for (int kk = 0; kk < 16; kk++) {
                    u64 a2[4];
                    #pragma unroll
                    for (int i = 0; i < 4; i++) { float a = As[kk][ty*4+i]; a2[i] = pack2f(a, a); }
                    ulonglong2 bg = *(const ulonglong2*)&Bs0[kk][tx*4];
                    ulonglong2 bu = *(const ulonglong2*)&Bs1[kk][tx*4];
                    #pragma unroll
                    for (int i = 0; i < 4; i++) {
                        fma2(accg[i][0], a2[i], bg.x); fma2(accg[i][1], a2[i], bg.y);
                        fma2(accu[i][0], a2[i], bu.x); fma2(accu[i][1], a2[i], bu.y);
                    }
                }
                __syncthreads();
            }
            #pragma unroll
            for (int i = 0; i < 4; i++) {
                int m = mb + ty*4 + i;
                if (m < rows) {
                    float g0,g1,g2,g3,u0,u1,u2,u3;
                    unpack2f(accg[i][0], g0, g1); unpack2f(accg[i][1], g2, g3);
                    unpack2f(accu[i][0], u0, u1); unpack2f(accu[i][1], u2, u3);
                    size_t base = (size_t)(start + m) * II + n0s + tx*4;
                    float a0 = siluf(g0)*u0, a1 = siluf(g1)*u1, a2v = siluf(g2)*u2, a3 = siluf(g3)*u3;
                    u32 hi, lo;
                    split2(a0, a1, hi, lo);
                    *(u32*)(d_act_hi + base) = hi; *(u32*)(d_act_lo + base) = lo;
                    split2(a2v, a3, hi, lo);
                    *(u32*)(d_act_hi + base + 2) = hi; *(u32*)(d_act_lo + base + 2) = lo;
                }
            }
            __syncthreads();
        }
    }
#endif
}

__global__ __launch_bounds__(NTHR)
#if HAS_TC
__cluster_dims__(1, 1, 1)
#endif
void k_moe2(const float* __restrict__ wd, float* __restrict__ out) {
    int tile = blockIdx.x;
    if (tile >= d_ntiles) return;
    extern __shared__ char smem[];
    int tid = threadIdx.x;
    int e = d_tile_e[tile], start = d_tile_start[tile], rows = d_tile_rows[tile];
    int n0 = blockIdx.y * NB;
    const float* B = wd + (size_t)e * II * HH;
    int* s_tok = (int*)(smem + SM_TOK);
    float* s_w = (float*)(smem + SM_W);
    if (tid < MT) {
        s_tok[tid] = (tid < rows) ? d_pair_token[start + tid] : 0;
        s_w[tid]   = (tid < rows) ? d_pair_w[start + tid] : 0.f;
    }
#if HAS_TC
    u32 sb = smem_u32(smem);
    int wid = tid >> 5, lid = tid & 31;
    if (tid == 0) mbar_init(sb + SM_MBAR, 1);
    if (wid == 0) { tmem_alloc(sb + SM_TMEM, 128); tmem_relinquish(); }
    __syncthreads();
    u32 tm; asm("ld.shared.b32 %0,[%1];" : "=r"(tm) : "r"(sb + SM_TMEM));

    int am = tid >> 2, aks = (tid & 3) * 16;
    const __nv_bfloat16* ah_p = d_act_hi + (size_t)(start + am) * II + aks;
    const __nv_bfloat16* al_p = d_act_lo + (size_t)(start + am) * II + aks;

    A2 a_r = load_a2(ah_p, al_p, 0);
    B4 b_r = load_b4(B, HH, 0, n0, tid);

    for (int c = 0; c < II/KC; c++) {
        int st = SM_BASE + (c & 1) * STG2;
        store_a2(smem, st + OF_AH, st + OF_AL, a_r, am, aks);
        store_b4(smem, st + OF_B0H, st + OF_B0L, b_r, tid);
        if (c + 1 < II/KC) {
            a_r = load_a2(ah_p, al_p, (c+1)*KC);
            b_r = load_b4(B, HH, (c+1)*KC, n0, tid);
        }
        fence_async();
        tc_fence_before();
        if (c > 0) mbar_wait(sb + SM_MBAR, (c - 1) & 1);
        __syncthreads();
        if (wid == 0) {
            tc_fence_after();
            u64 ah = sdesc(sb + st + OF_AH), al = sdesc(sb + st + OF_AL);
            u64 bh = sdesc(sb + st + OF_B0H), bl = sdesc(sb + st + OF_B0L);
            if (elect_one()) {
                #pragma unroll
                for (int s = 0; s < 4; s++) {
                    u32 en = (c == 0 && s == 0) ? 0u : 1u;
                    mma_bf16(tm, ah + s*2, bh + s*2, IDESC_N128, en);
                    mma_bf16(tm, ah + s*2, bl + s*2, IDESC_N128, 1u);
                    mma_bf16(tm, al + s*2, bh + s*2, IDESC_N128, 1u);
                }
                mma_commit(sb + SM_MBAR);
            }
        }
    }
    mbar_wait(sb + SM_MBAR, (II/KC - 1) & 1);
    tc_fence_after();
    if (wid < 4) {
        int m = wid*32 + lid;
        #pragma unroll
        for (int pass = 0; pass < 4; pass++) {
            u32 r[32];
            LDTM_X32(r, tm + pass*32);
            tc_wait_ld();
            if (m < rows) {
                float w = s_w[m];
                float* o = out + (size_t)s_tok[m] * HH + n0 + pass*32;
                #pragma unroll
                for (int j = 0; j < 32; j++)
                    atomicAdd(o + j, w * __uint_as_float(r[j]));
            }
        }
    }
    __syncthreads();
    if (wid == 0) tmem_dealloc(tm, 128);
#else
    __syncthreads();
    int t2 = tid & 255;
    int tx = t2 & 15, ty = t2 >> 4;
    int la_m = t2 >> 2, la_k = (t2 & 3) << 2;
    int lb_k = t2 >> 4, lb_n = (t2 & 15) << 2;
    float (*As)[66]  = (float(*)[66])(smem + 2048);
    float (*Bs0)[64] = (float(*)[64])(smem + 2048 + 16*66*4);
    for (int ns = 0; ns < NB/64; ns++) {
        int n0s = n0 + ns*64;
        for (int sub = 0; sub < 2; sub++) {
            int mb = sub * 64;
            const __nv_bfloat16* ahp = d_act_hi + (size_t)(start + mb + la_m) * II + la_k;
            const __nv_bfloat16* alp = d_act_lo + (size_t)(start + mb + la_m) * II + la_k;
            u64 acc[4][2];
            #pragma unroll
            for (int i = 0; i < 4; i++) { acc[i][0] = 0ull; acc[i][1] = 0ull; }
            for (int k0 = 0; k0 < II; k0 += 16) {
                #pragma unroll
                for (int j = 0; j < 4; j++)
                    As[la_k+j][la_m] = __bfloat162float(ahp[k0+j]) + __bfloat162float(alp[k0+j]);
                *(float4*)&Bs0[lb_k][lb_n] = *(const float4*)(B + (size_t)(k0 + lb_k) * HH + n0s + lb_n);
                __syncthreads();
                #pragma unroll
                for (int kk = 0; kk < 16; kk++) {
                    u64 a2[4];
                    #pragma unroll
                    for (int i = 0; i < 4; i++) { float a = As[kk][ty*4+i]; a2[i] = pack2f(a, a); }
                    ulonglong2 b = *(const ulonglong2*)&Bs0[kk][tx*4];
                    #pragma unroll
                    for (int i = 0; i < 4; i++) { fma2(acc[i][0], a2[i], b.x); fma2(acc[i][1], a2[i], b.y); }
                }
                __syncthreads();
            }
            if (tid < 256) {
                #pragma unroll
                for (int i = 0; i < 4; i++) {
                    int m = mb + ty*4 + i;
                    if (m < rows) {
                        float w = s_w[m];
                        float* o = out + (size_t)s_tok[m] * HH + n0s + tx*4;
                        float v0,v1,v2,v3;
                        unpack2f(acc[i][0], v0, v1); unpack2f(acc[i][1], v2, v3);
                        atomicAdd(o+0, w*v0); atomicAdd(o+1, w*v1);
                        atomicAdd(o+2, w*v2); atomicAdd(o+3, w*v3);
                    }
                }
            }
            __syncthreads();
        }
    }
#endif
}

__global__ __launch_bounds__(NTHR)
#if HAS_TC
__cluster_dims__(1, 1, 1)
#endif
void k_shared1(const float* __restrict__ x,
               const float* __restrict__ wg,
               const float* __restrict__ wu) {
    extern __shared__ char smem[];
    int tid = threadIdx.x;
    int m0 = blockIdx.x * MT, n0 = blockIdx.y * NB;
#if HAS_TC
    u32 sb = smem_u32(smem);
    int wid = tid >> 5, lid = tid & 31;
    if (tid == 0) mbar_init(sb + SM_MBAR, 1);
    if (wid == 0) { tmem_alloc(sb + SM_TMEM, 256); tmem_relinquish(); }
    __syncthreads();
    u32 tm; asm("ld.shared.b32 %0,[%1];" : "=r"(tm) : "r"(sb + SM_TMEM));

    int am = tid >> 2, aks = (tid & 3) * 16;
    const float* arow = x + (size_t)(m0 + am) * HH + aks;

    B4 bg_r = load_b4(wg, ISH, 0, n0, tid);
    B4 bu_r = load_b4(wu, ISH, 0, n0, tid);

    for (int c = 0; c < HH/KC; c++) {
        int st = SM_BASE + (c & 1) * STG1;
        #pragma unroll
        for (int r = 0; r < 4; r++) {
            float4 v = *(const float4*)(arow + c*KC + r*4);
            u32 h01, l01, h23, l23;
            split2(v.x, v.y, h01, l01); split2(v.z, v.w, h23, l23);
            u32 sw = sw128((u32)(am*128 + (aks + r*4)*2));
            *(uint2*)(smem + st + OF_AH + sw) = make_uint2(h01, h23);
            *(uint2*)(smem + st + OF_AL + sw) = make_uint2(l01, l23);
        }
        store_b4(smem, st + OF_B0H, st + OF_B0L, bg_r, tid);
        store_b4(smem, st + OF_B1H, st + OF_B1L, bu_r, tid);
        if (c + 1 < HH/KC) {
            bg_r = load_b4(wg, ISH, (c+1)*KC, n0, tid);
            bu_r = load_b4(wu, ISH, (c+1)*KC, n0, tid);
        }
        fence_async();
        tc_fence_before();
        if (c > 0) mbar_wait(sb + SM_MBAR, (c - 1) & 1);
        __syncthreads();
        if (wid == 0) {
            tc_fence_after();
            u64 ah = sdesc(sb + st + OF_AH), al = sdesc(sb + st + OF_AL);
            u64 gh = sdesc(sb + st + OF_B0H), gl = sdesc(sb + st + OF_B0L);
            u64 uh = sdesc(sb + st + OF_B1H), ul = sdesc(sb + st + OF_B1L);
            if (elect_one()) {
                #pragma unroll
                for (int s = 0; s < 4; s++) {
                    u32 en = (c == 0 && s == 0) ? 0u : 1u;
                    mma_bf16(tm +   0, ah + s*2, gh + s*2, IDESC_N128, en);
                    mma_bf16(tm +   0, ah + s*2, gl + s*2, IDESC_N128, 1u);
                    mma_bf16(tm +   0, al + s*2, gh + s*2, IDESC_N128, 1u);
                    mma_bf16(tm + 128, ah + s*2, uh + s*2, IDESC_N128, en);
                    mma_bf16(tm + 128, ah + s*2, ul + s*2, IDESC_N128, 1u);
                    mma_bf16(tm + 128, al + s*2, uh + s*2, IDESC_N128, 1u);
                }
                mma_commit(sb + SM_MBAR);
            }
        }
    }
    mbar_wait(sb + SM_MBAR, (HH/KC - 1) & 1);
    tc_fence_after();
    if (wid < 4) {
        int m = wid*32 + lid;
        #pragma unroll
        for (int pass = 0; pass < 4; pass++) {
            u32 rg[32], ru[32];
            LDTM_X32(rg, tm + pass*32);
            LDTM_X32(ru, tm + 128 + pass*32);
            tc_wait_ld();
            size_t base = (size_t)(m0 + m) * ISH + n0 + pass*32;
            #pragma unroll
            for (int j = 0; j < 32; j += 2) {
                float g0 = __uint_as_float(rg[j]),   u0 = __uint_as_float(ru[j]);
                float g1 = __uint_as_float(rg[j+1]), u1 = __uint_as_float(ru[j+1]);
                float a0 = siluf(g0)*u0, a1 = siluf(g1)*u1;
                u32 hi, lo; split2(a0, a1, hi, lo);
                *(u32*)(d_shact_hi + base + j) = hi;
                *(u32*)(d_shact_lo + base + j) = lo;
            }
        }
    }
    __syncthreads();
    if (wid == 0) tmem_dealloc(tm, 256);
#else
    int t2 = tid & 255;
    int tx = t2 & 15, ty = t2 >> 4;
    int la_m = t2 >> 2, la_k = (t2 & 3) << 2;
    int lb_k = t2 >> 4, lb_n = (t2 & 15) << 2;
    float (*As)[66]  = (float(*)[66])(smem + 2048);
    float (*Bs0)[64] = (float(*)[64])(smem + 2048 + 16*66*4);
    float (*Bs1)[64] = (float(*)[64])(smem + 2048 + 16*66*4 + 16*64*4);
    for (int ns = 0; ns < NB/64; ns++) {
        int n0s = n0 + ns*64;
        for (int sub = 0; sub < 2; sub++) {
            int mb = sub * 64;
            const float* arow = x + (size_t)(m0 + mb + la_m) * HH + la_k;
            u64 accg[4][2], accu[4][2];
            #pragma unroll
            for (int i = 0; i < 4; i++) { accg[i][0]=0ull; accg[i][1]=0ull; accu[i][0]=0ull; accu[i][1]=0ull; }
            for (int k0 = 0; k0 < HH; k0 += 16) {
                float4 av = *(const float4*)(arow + k0);
                As[la_k+0][la_m] = av.x; As[la_k+1][la_m] = av.y;
                As[la_k+2][la_m] = av.z; As[la_k+3][la_m] = av.w;
                *(float4*)&Bs0[lb_k][lb_n] = *(const float4*)(wg + (size_t)(k0 + lb_k) * ISH + n0s + lb_n);
                *(float4*)&Bs1[lb_k][lb_n] = *(const float4*)(wu + (size_t)(k0 + lb_k) * ISH + n0s + lb_n);
                __syncthreads();
                #pragma unroll
                for (int kk = 0; kk < 16; kk++) {
                    u64 a2[4];
                    #pragma unroll
                    for (int i = 0; i < 4; i++) { float a = As[kk][ty*4+i]; a2[i] = pack2f(a, a); }
                    ulonglong2 bg = *(const ulonglong2*)&Bs0[kk][tx*4];
                    ulonglong2 bu = *(const ulonglong2*)&Bs1[kk][tx*4];
                    #pragma unroll
                    for (int i = 0; i < 4; i++) {
                        fma2(accg[i][0], a2[i], bg.x); fma2(accg[i][1], a2[i], bg.y);
                        fma2(accu[i][0], a2[i], bu.x); fma2(accu[i][1], a2[i], bu.y);
                    }
                }
                __syncthreads();
            }
            #pragma unroll
            for (int i = 0; i < 4; i++) {
                float g0,g1,g2,g3,u0,u1,u2,u3;
                unpack2f(accg[i][0], g0, g1); unpack2f(accg[i][1], g2, g3);
                unpack2f(accu[i][0], u0, u1); unpack2f(accu[i][1], u2, u3);
                float a0 = siluf(g0)*u0, a1 = siluf(g1)*u1, a2v = siluf(g2)*u2, a3 = siluf(g3)*u3;
                size_t base = (size_t)(m0 + mb + ty*4 + i) * ISH + n0s + tx*4;
                u32 hi, lo;
                split2(a0, a1, hi, lo);
                *(u32*)(d_shact_hi + base) = hi; *(u32*)(d_shact_lo + base) = lo;
                split2(a2v, a3, hi, lo);
                *(u32*)(d_shact_hi + base + 2) = hi; *(u32*)(d_shact_lo + base + 2) = lo;
            }
            __syncthreads();
        }
    }
#endif
}

__global__ __launch_bounds__(NTHR)
#if HAS_TC
__cluster_dims__(1, 1, 1)
#endif
void k_shared2(const float* __restrict__ wd, float* __restrict__ out) {
    extern __shared__ char smem[];
    int tid = threadIdx.x;
    int m0 = blockIdx.x * MT, n0 = blockIdx.y * NB;
#if HAS_TC
    u32 sb = smem_u32(smem);
    int wid = tid >> 5, lid = tid & 31;
    if (tid == 0) mbar_init(sb + SM_MBAR, 1);
    if (wid == 0) { tmem_alloc(sb + SM_TMEM, 128); tmem_relinquish(); }
    __syncthreads();
    u32 tm; asm("ld.shared.b32 %0,[%1];" : "=r"(tm) : "r"(sb + SM_TMEM));

    int am = tid >> 2, aks = (tid & 3) * 16;
    const __nv_bfloat16* ah_p = d_shact_hi + (size_t)(m0 + am) * ISH + aks;
    const __nv_bfloat16* al_p = d_shact_lo + (size_t)(m0 + am) * ISH + aks;

    A2 a_r = load_a2(ah_p, al_p, 0);
    B4 b_r = load_b4(wd, HH, 0, n0, tid);

    for (int c = 0; c < ISH/KC; c++) {
        int st = SM_BASE + (c & 1) * STG2;
        store_a2(smem, st + OF_AH, st + OF_AL, a_r, am, aks);
        store_b4(smem, st + OF_B0H, st + OF_B0L, b_r, tid);
        if (c + 1 < ISH/KC) {
            a_r = load_a2(ah_p, al_p, (c+1)*KC);
            b_r = load_b4(wd, HH, (c+1)*KC, n0, tid);
        }
        fence_async();
        tc_fence_before();
        if (c > 0) mbar_wait(sb + SM_MBAR, (c - 1) & 1);
        __syncthreads();
        if (wid == 0) {
            tc_fence_after();
            u64 ah = sdesc(sb + st + OF_AH), al = sdesc(sb + st + OF_AL);
            u64 bh = sdesc(sb + st + OF_B0H), bl = sdesc(sb + st + OF_B0L);
            if (elect_one()) {
                #pragma unroll
                for (int s = 0; s < 4; s++) {
                    u32 en = (c == 0 && s == 0) ? 0u : 1u;
                    mma_bf16(tm, ah + s*2, bh + s*2, IDESC_N128, en);
                    mma_bf16(tm, ah + s*2, bl + s*2, IDESC_N128, 1u);
                    mma_bf16(tm, al + s*2, bh + s*2, IDESC_N128, 1u);
                }
                mma_commit(sb + SM_MBAR);
            }
        }
    }
    mbar_wait(sb + SM_MBAR, (ISH/KC - 1) & 1);
    tc_fence_after();
    if (wid < 4) {
        int m = wid*32 + lid;
        #pragma unroll
        for (int pass = 0; pass < 4; pass++) {
            u32 r[32];
            LDTM_X32(r, tm + pass*32);
            tc_wait_ld();
            float* o = out + (size_t)(m0 + m) * HH + n0 + pass*32;
            #pragma unroll
            for (int j = 0; j < 32; j += 4)
                *(float4*)(o + j) = make_float4(
                    __uint_as_float(r[j]),   __uint_as_float(r[j+1]),
                    __uint_as_float(r[j+2]), __uint_as_float(r[j+3]));
        }
    }
    __syncthreads();
    if (wid == 0) tmem_dealloc(tm, 128);
#else
    int t2 = tid & 255;
    int tx = t2 & 15, ty = t2 >> 4;
    int la_m = t2 >> 2, la_k = (t2 & 3) << 2;
    int lb_k = t2 >> 4, lb_n = (t2 & 15) << 2;
    float (*As)[66]  = (float(*)[66])(smem + 2048);
    float (*Bs0)[64] = (float(*)[64])(smem + 2048 + 16*66*4);
    for (int ns = 0; ns < NB/64; ns++) {
        int n0s = n0 + ns*64;
        for (int sub = 0; sub < 2; sub++) {
            int mb = sub * 64;
            const __nv_bfloat16* ahp = d_shact_hi + (size_t)(m0 + mb + la_m) * ISH + la_k;
            const __nv_bfloat16* alp = d_shact_lo + (size_t)(m0 + mb + la_m) * ISH + la_k;
            u64 acc[4][2];
            #pragma unroll
            for (int i = 0; i < 4; i++) { acc[i][0] = 0ull; acc[i][1] = 0ull; }
            for (int k0 = 0; k0 < ISH; k0 += 16) {
                #pragma unroll
                for (int j = 0; j < 4; j++)
                    As[la_k+j][la_m] = __bfloat162float(ahp[k0+j]) + __bfloat162float(alp[k0+j]);
                *(float4*)&Bs0[lb_k][lb_n] = *(const float4*)(wd + (size_t)(k0 + lb_k) * HH + n0s + lb_n);
                __syncthreads();
                #pragma unroll
                for (int kk = 0; kk < 16; kk++) {
                    u64 a2[4];
                    #pragma unroll
                    for (int i = 0; i < 4; i++) { float a = As[kk][ty*4+i]; a2[i] = pack2f(a, a); }
                    ulonglong2 b = *(const ulonglong2*)&Bs0[kk][tx*4];
                    #pragma unroll
                    for (int i = 0; i < 4; i++) { fma2(acc[i][0], a2[i], b.x); fma2(acc[i][1], a2[i], b.y); }
                }
                __syncthreads();
            }
            if (tid < 256) {
                #pragma unroll
                for (int i = 0; i < 4; i++) {
                    float v0,v1,v2,v3;
                    unpack2f(acc[i][0], v0, v1); unpack2f(acc[i][1], v2, v3);
                    float* o = out + (size_t)(m0 + mb + ty*4 + i) * HH + n0s + tx*4;
                    o[0] = v0; o[1] = v1; o[2] = v2; o[3] = v3;
                }
            }
            __syncthreads();
        }
    }
#endif
}

extern "C" void kernel_launch(void* const* d_in, const int* in_sizes, int n_in,
                              void* d_out, int out_size) {
    const float* x    = (const float*)d_in[0];
    const float* gw   = (const float*)d_in[1];
    const float* bias = (const float*)d_in[2];
    const float* wg   = (const float*)d_in[3];
    const float* wu   = (const float*)d_in[4];
    const float* wd   = (const float*)d_in[5];
    const float* wsg  = (const float*)d_in[6];
    const float* wsu  = (const float*)d_in[7];
    const float* wsd  = (const float*)d_in[8];
    float* out = (float*)d_out;

    cudaFuncSetAttribute(k_moe1,    cudaFuncAttributeMaxDynamicSharedMemorySize, SMEM_SZ1);
    cudaFuncSetAttribute(k_moe2,    cudaFuncAttributeMaxDynamicSharedMemorySize, SMEM_SZ2);
    cudaFuncSetAttribute(k_shared1, cudaFuncAttributeMaxDynamicSharedMemorySize, SMEM_SZ1);
    cudaFuncSetAttribute(k_shared2, cudaFuncAttributeMaxDynamicSharedMemorySize, SMEM_SZ2);

    k_gate<<<16, 256>>>(x, gw);
    k_route<<<4, 256>>>(bias);
    k_scan<<<1, 64>>>();
    k_scatter<<<NPAIR/256, 256>>>();
    k_moe1<<<dim3(MAXTILES, II/NB), NTHR, SMEM_SZ1>>>(x, wg, wu);
    k_shared1<<<dim3(TT/MT, ISH/NB), NTHR, SMEM_SZ1>>>(x, wsg, wsu);
    k_shared2<<<dim3(TT/MT, HH/NB), NTHR, SMEM_SZ2>>>(wsd, out);
    k_moe2<<<dim3(MAXTILES, HH/NB), NTHR, SMEM_SZ2>>>(wd, out);
}